// round 15
// baseline (speedup 1.0000x reference)
#include <cuda_runtime.h>
#include <cuda_bf16.h>
#include <math.h>

#define B_ 16
#define C_ 128
#define L_ 1024
#define H_ 8
#define DK_ 16
#define NCONV_ 4
#define NTOK (B_*L_)
#define NELEM (B_*L_*C_)

// ---------------- scratch ----------------
__device__ float g_cur[NELEM];
__device__ float g_ln[NELEM];
__device__ float g_t1[NELEM];
__device__ float g_q[NELEM];
__device__ float g_k[NELEM];
__device__ float g_v[NELEM];
__device__ int   g_mask_int;

// ---------------- asm helpers ----------------
#define LDMX4(r0,r1,r2,r3,addr) \
  asm volatile("ldmatrix.sync.aligned.m8n8.x4.shared.b16 {%0,%1,%2,%3},[%4];" \
    : "=r"(r0),"=r"(r1),"=r"(r2),"=r"(r3) : "r"(addr))

#define LDMX4T(r0,r1,r2,r3,addr) \
  asm volatile("ldmatrix.sync.aligned.m8n8.x4.trans.shared.b16 {%0,%1,%2,%3},[%4];" \
    : "=r"(r0),"=r"(r1),"=r"(r2),"=r"(r3) : "r"(addr))

#define MMA_BF16_Z(d,a0,a1,a2,a3,b0,b1) \
  asm volatile("mma.sync.aligned.m16n8k16.row.col.f32.bf16.bf16.f32 " \
    "{%0,%1,%2,%3},{%4,%5,%6,%7},{%8,%9},{%10,%11,%12,%13};" \
    : "=f"(d[0]),"=f"(d[1]),"=f"(d[2]),"=f"(d[3]) \
    : "r"(a0),"r"(a1),"r"(a2),"r"(a3),"r"(b0),"r"(b1), \
      "f"(0.f),"f"(0.f),"f"(0.f),"f"(0.f))

#define MMA_BF16(d,a0,a1,a2,a3,b0,b1) \
  asm volatile("mma.sync.aligned.m16n8k16.row.col.f32.bf16.bf16.f32 " \
    "{%0,%1,%2,%3},{%4,%5,%6,%7},{%8,%9},{%0,%1,%2,%3};" \
    : "+f"(d[0]),"+f"(d[1]),"+f"(d[2]),"+f"(d[3]) \
    : "r"(a0),"r"(a1),"r"(a2),"r"(a3),"r"(b0),"r"(b1))

#define MMA_TF32(d,a,b) \
  asm volatile("mma.sync.aligned.m16n8k8.row.col.f32.tf32.tf32.f32 " \
    "{%0,%1,%2,%3},{%4,%5,%6,%7},{%8,%9},{%0,%1,%2,%3};" \
    : "+f"(d[0]),"+f"(d[1]),"+f"(d[2]),"+f"(d[3]) \
    : "r"((a)[0]),"r"((a)[1]),"r"((a)[2]),"r"((a)[3]),"r"((b)[0]),"r"((b)[1]))

#define CP_ASYNC16(saddr, gptr) \
  asm volatile("cp.async.ca.shared.global [%0],[%1],16;" :: "r"(saddr), "l"(gptr))
#define CP_COMMIT() asm volatile("cp.async.commit_group;")
#define CP_WAIT0()  asm volatile("cp.async.wait_group 0;")

__device__ __forceinline__ unsigned cvt_tf32(float f) {
    unsigned u; asm("cvt.rna.tf32.f32 %0,%1;" : "=r"(u) : "f"(f)); return u;
}
__device__ __forceinline__ unsigned pack_bf16(float a, float b) {
    __nv_bfloat162 t = __floats2bfloat162_rn(a, b);
    return *(unsigned*)&t;
}
__device__ __forceinline__ unsigned smem_u32(const void* p) {
    return (unsigned)__cvta_generic_to_shared(p);
}

// FMA-pipe exp: magic-number range reduction + deg-5 2^f poly.
// Valid for x <= ~10; masked x=-1e30 clamps to exp(-87) ~ 1.6e-38 (harmless).
__device__ __forceinline__ float fexp(float x) {
    const float log2e = 1.4426950408889634f;
    const float magic = 12582912.0f;            // 2^23 + 2^22
    float xs = fmaxf(x, -87.f);
    float t  = fmaf(xs, log2e, magic);          // int part in low mantissa
    float fi = t - magic;
    float f  = fmaf(xs, log2e, -fi);            // f in [-0.5, 0.5]
    float p  = 1.3333558146428443e-3f;
    p = fmaf(p, f, 9.6181291976353954e-3f);
    p = fmaf(p, f, 5.5504108664821580e-2f);
    p = fmaf(p, f, 2.4022650695910071e-1f);
    p = fmaf(p, f, 6.9314718055994531e-1f);
    p = fmaf(p, f, 1.0f);
    unsigned sb = (unsigned)(__float_as_int(t) - 0x4B400000 + 127) << 23;
    return p * __int_as_float(sb);
}

__device__ __forceinline__ void ln_row(float4& v, const float4& gg, const float4& gb) {
    float s  = v.x + v.y + v.z + v.w;
    float sq = v.x*v.x + v.y*v.y + v.z*v.z + v.w*v.w;
    #pragma unroll
    for (int off = 16; off; off >>= 1) {
        s  += __shfl_xor_sync(0xffffffffu, s,  off);
        sq += __shfl_xor_sync(0xffffffffu, sq, off);
    }
    const float mean = s * (1.f/128.f);
    const float var  = sq * (1.f/128.f) - mean * mean;
    const float r    = rsqrtf(var + 1e-5f);
    v.x = (v.x - mean) * r * gg.x + gb.x;
    v.y = (v.y - mean) * r * gg.y + gb.y;
    v.z = (v.z - mean) * r * gg.z + gb.z;
    v.w = (v.w - mean) * r * gg.w + gb.w;
}

// async-stage [128][128] fp32 -> smem [128][132] raw bits (tf32 via HW trunc)
template<int NT>
__device__ __forceinline__ void stage_W_async(const float* __restrict__ W, float* Ws, int tid) {
    #pragma unroll
    for (int i = 0; i < 4096 / NT; i++) {
        const int f4 = tid + i * NT;
        const int row = f4 >> 5, c = (f4 & 31) * 4;
        CP_ASYNC16(smem_u32(&Ws[row * 132 + c]), W + (size_t)row * C_ + c);
    }
}

// 64x128x128 MMA, 16 warps, warp tile 16x32 (mw=warp>>2 rows, nw=warp&3 cols)
__device__ __forceinline__ void mma_64x128(
    const unsigned* Au, const unsigned* Wu, int mw, int nw, int grp, int tig,
    float acc[4][4])
{
    const int r = mw * 16 + grp;
    #pragma unroll
    for (int ks = 0; ks < 16; ks++) {
        const int kb = ks * 8;
        unsigned af[4], bf[4][2];
        af[0] = Au[r * 132 + kb + tig];
        af[1] = Au[(r + 8) * 132 + kb + tig];
        af[2] = Au[r * 132 + kb + tig + 4];
        af[3] = Au[(r + 8) * 132 + kb + tig + 4];
        #pragma unroll
        for (int nt = 0; nt < 4; nt++) {
            const int rr = nw * 32 + nt * 8 + grp;
            bf[nt][0] = Wu[rr * 132 + kb + tig];
            bf[nt][1] = Wu[rr * 132 + kb + tig + 4];
        }
        #pragma unroll
        for (int nt = 0; nt < 4; nt++)
            MMA_TF32(acc[nt], af, bf[nt]);
    }
}

// 128x128x128 MMA (16 warps, warp tile 32x32): acc[2][4][4]
__device__ __forceinline__ void mma_w32x32(
    const unsigned* Au, const unsigned* Wu, int mw, int nw, int grp, int tig,
    float acc[2][4][4])
{
    #pragma unroll
    for (int ks = 0; ks < 16; ks++) {
        const int kb = ks * 8;
        unsigned af[2][4], bf[4][2];
        #pragma unroll
        for (int mt = 0; mt < 2; mt++) {
            const int r = mw * 32 + mt * 16 + grp;
            af[mt][0] = Au[r * 132 + kb + tig];
            af[mt][1] = Au[(r + 8) * 132 + kb + tig];
            af[mt][2] = Au[r * 132 + kb + tig + 4];
            af[mt][3] = Au[(r + 8) * 132 + kb + tig + 4];
        }
        #pragma unroll
        for (int nt = 0; nt < 4; nt++) {
            const int r = nw * 32 + nt * 8 + grp;
            bf[nt][0] = Wu[r * 132 + kb + tig];
            bf[nt][1] = Wu[r * 132 + kb + tig + 4];
        }
        #pragma unroll
        for (int mt = 0; mt < 2; mt++)
            #pragma unroll
            for (int nt = 0; nt < 4; nt++)
                MMA_TF32(acc[mt][nt], af[mt], bf[nt]);
    }
}

// ---------------- [B,C,L] -> [B,L,C] + pos encoding (+ mask detect in block 0) ----------------
__global__ void k_in2work(const float* __restrict__ x, float* __restrict__ out,
                          const unsigned char* __restrict__ m) {
    __shared__ float tile[32][33];
    __shared__ int sdet;
    const int b  = blockIdx.z;
    const int l0 = blockIdx.x * 32;
    const int c0 = blockIdx.y * 32;
    const int tx = threadIdx.x, ty = threadIdx.y;
    const int tid = ty * 32 + tx;
    const bool det = (blockIdx.x == 0 && blockIdx.y == 0 && blockIdx.z == 0);
    if (det) {
        if (tid == 0) sdet = 0;
        __syncthreads();
        int nz = 0;
        for (int i = tid; i < NTOK; i += 256)
            if ((i & 3) && m[i]) nz = 1;
        if (nz) atomicOr(&sdet, 1);
        __syncthreads();
        if (tid == 0) g_mask_int = (sdet == 0) ? 1 : 0;
    }
    #pragma unroll
    for (int j = 0; j < 4; j++)
        tile[ty + 8*j][tx] = x[((size_t)b*C_ + (c0 + ty + 8*j))*L_ + l0 + tx];
    __syncthreads();
    const int c = c0 + tx;
    const float fi = (float)c;
    float freq, phase;
    if (c & 1) { freq = -powf(10000.f, (1.f - fi) * (1.f/128.f)); phase = 1.57079632679489662f; }
    else       { freq =  powf(10000.f, -fi * (1.f/128.f));        phase = 0.f; }
    #pragma unroll
    for (int j = 0; j < 4; j++) {
        const int l = l0 + ty + 8*j;
        out[((size_t)b*L_ + l)*C_ + c] = tile[tx][ty + 8*j] + sinf((float)l * freq + phase);
    }
}

// ---------------- [B,L,C] -> [B,C,L] ----------------
__global__ void k_work2out(const float* __restrict__ in, float* __restrict__ out) {
    __shared__ float tile[32][33];
    const int b  = blockIdx.z;
    const int l0 = blockIdx.x * 32;
    const int c0 = blockIdx.y * 32;
    const int tx = threadIdx.x, ty = threadIdx.y;
    #pragma unroll
    for (int j = 0; j < 4; j++)
        tile[ty + 8*j][tx] = in[((size_t)b*L_ + (l0 + ty + 8*j))*C_ + c0 + tx];
    __syncthreads();
    #pragma unroll
    for (int j = 0; j < 4; j++)
        out[((size_t)b*C_ + (c0 + ty + 8*j))*L_ + l0 + tx] = tile[tx][ty + 8*j];
}

// =====================================================================
// Fused conv block (R13 winner): 64-token tile, sliding-window conv,
// 16-warp 16x32 MMA. FROZEN.
// =====================================================================
__global__ void __launch_bounds__(512, 2) k_convblock(
    const float* __restrict__ in, const float* __restrict__ dw,
    const float* __restrict__ pw, const float* __restrict__ pb,
    const float* __restrict__ g,  const float* __restrict__ bb,
    float* __restrict__ out)
{
    extern __shared__ float sm[];
    float* y   = sm;                       // [70][132]; rows 0..63 become As
    float* Ws  = y  + 70 * 132;            // [128][132] raw fp32
    float* dwT = Ws + 128 * 132;           // [7][128]
    const int tid = threadIdx.x;
    const int b  = blockIdx.x >> 4;
    const int l0 = (blockIdx.x & 15) * 64;
    const int warp = tid >> 5, lane = tid & 31;

    stage_W_async<512>(pw, Ws, tid);
    CP_COMMIT();
    for (int i = tid; i < 896; i += 512) {
        const int k = i >> 7, c = i & 127;
        dwT[i] = dw[c * 7 + k];
    }
    {
        const float4 gg = *(const float4*)(g  + lane * 4);
        const float4 gb = *(const float4*)(bb + lane * 4);
        for (int r = warp; r < 70; r += 16) {
            const int l = l0 - 3 + r;
            float4 v = make_float4(0.f, 0.f, 0.f, 0.f);
            if (l >= 0 && l < L_) {
                v = *(const float4*)(in + ((size_t)(b * L_ + l)) * C_ + lane * 4);
                ln_row(v, gg, gb);
            } else {
                ln_row(v, gg, gb);   // keep warp converged
                v = make_float4(0.f, 0.f, 0.f, 0.f);
            }
            *(float4*)&y[r * 132 + lane * 4] = v;
        }
    }
    CP_WAIT0();
    __syncthreads();

    // sliding-window depthwise conv (thread = channel pair x 8 l-positions)
    uint2 racc[8];
    {
        const int p  = tid & 63;
        const int lb = (tid >> 6) * 8;
        const int cb = p * 2;
        float2 wk[7];
        #pragma unroll
        for (int k = 0; k < 7; k++) wk[k] = *(const float2*)&dwT[k * 128 + cb];
        float2 w0 = *(const float2*)&y[(lb + 0) * 132 + cb];
        float2 w1 = *(const float2*)&y[(lb + 1) * 132 + cb];
        float2 w2 = *(const float2*)&y[(lb + 2) * 132 + cb];
        float2 w3 = *(const float2*)&y[(lb + 3) * 132 + cb];
        float2 w4 = *(const float2*)&y[(lb + 4) * 132 + cb];
        float2 w5 = *(const float2*)&y[(lb + 5) * 132 + cb];
        #pragma unroll
        for (int i = 0; i < 8; i++) {
            const float2 w6 = *(const float2*)&y[(lb + i + 6) * 132 + cb];
            float ax = wk[0].x * w0.x + wk[1].x * w1.x + wk[2].x * w2.x
                     + wk[3].x * w3.x + wk[4].x * w4.x + wk[5].x * w5.x
                     + wk[6].x * w6.x;
            float ay = wk[0].y * w0.y + wk[1].y * w1.y + wk[2].y * w2.y
                     + wk[3].y * w3.y + wk[4].y * w4.y + wk[5].y * w5.y
                     + wk[6].y * w6.y;
            racc[i].x = cvt_tf32(ax);
            racc[i].y = cvt_tf32(ay);
            w0 = w1; w1 = w2; w2 = w3; w3 = w4; w4 = w5; w5 = w6;
        }
    }
    __syncthreads();   // all conv reads of y done
    {
        const int p  = tid & 63;
        const int lb = (tid >> 6) * 8;
        const int cb = p * 2;
        #pragma unroll
        for (int i = 0; i < 8; i++)
            *(uint2*)&y[(lb + i) * 132 + cb] = racc[i];
    }
    __syncthreads();

    const int grp = lane >> 2, tig = lane & 3;
    const int mw = warp >> 2, nw = warp & 3;
    float acc[4][4];
    #pragma unroll
    for (int nt = 0; nt < 4; nt++)
        #pragma unroll
        for (int q = 0; q < 4; q++) acc[nt][q] = 0.f;

    mma_64x128((const unsigned*)y, (const unsigned*)Ws, mw, nw, grp, tig, acc);

    #pragma unroll
    for (int nt = 0; nt < 4; nt++) {
        const int col = nw * 32 + nt * 8 + tig * 2;
        const float2 bv = *(const float2*)(pb + col);
        const int rl = mw * 16 + grp;
        const size_t r0 = (size_t)(b * L_ + l0 + rl) * C_ + col;
        const size_t r1 = (size_t)(b * L_ + l0 + rl + 8) * C_ + col;
        float2 v0 = make_float2(fmaxf(acc[nt][0] + bv.x, 0.f), fmaxf(acc[nt][1] + bv.y, 0.f));
        float2 v1 = make_float2(fmaxf(acc[nt][2] + bv.x, 0.f), fmaxf(acc[nt][3] + bv.y, 0.f));
        const float2 q0 = *(const float2*)(in + r0);
        const float2 q1 = *(const float2*)(in + r1);
        v0.x += q0.x; v0.y += q0.y; v1.x += q1.x; v1.y += q1.y;
        *(float2*)(out + r0) = v0;
        *(float2*)(out + r1) = v1;
    }
}

// =====================================================================
// tf32 GEMM, 128-token tiles, cp.async staging
// =====================================================================
template<bool LNA, bool RELU, bool ADDRES>
__global__ void __launch_bounds__(512) k_gemm_tf32(
    const float* __restrict__ A, const float* __restrict__ W,
    const float* __restrict__ bias, const float* __restrict__ res,
    float* __restrict__ out,
    const float* __restrict__ g, const float* __restrict__ bb)
{
    extern __shared__ float sm[];
    float* As = sm;                        // [128][132]
    float* Ws = sm + 128 * 132;            // [128][132]
    const int tid = threadIdx.x;
    const int m0 = blockIdx.x * 128;
    const int warp = tid >> 5, lane = tid & 31;

    stage_W_async<512>(W, Ws, tid);
    if (LNA) {
        CP_COMMIT();
        const float4 gg = *(const float4*)(g  + lane * 4);
        const float4 gb = *(const float4*)(bb + lane * 4);
        for (int r = warp; r < 128; r += 16) {
            float4 v = *(const float4*)(A + (size_t)(m0 + r) * C_ + lane * 4);
            ln_row(v, gg, gb);
            uint4 u;
            u.x = cvt_tf32(v.x); u.y = cvt_tf32(v.y); u.z = cvt_tf32(v.z); u.w = cvt_tf32(v.w);
            *(uint4*)&As[r * 132 + lane * 4] = u;
        }
    } else {
        #pragma unroll
        for (int i = 0; i < 8; i++) {
            const int f4 = tid + i * 512;
            const int row = f4 >> 5, c = (f4 & 31) * 4;
            CP_ASYNC16(smem_u32(&As[row * 132 + c]), A + (size_t)(m0 + row) * C_ + c);
        }
        CP_COMMIT();
    }
    CP_WAIT0();
    __syncthreads();

    const int grp = lane >> 2, tig = lane & 3;
    const int mw = warp >> 2, nw = warp & 3;
    float acc[2][4][4];
    #pragma unroll
    for (int mt = 0; mt < 2; mt++)
        #pragma unroll
        for (int nt = 0; nt < 4; nt++)
            #pragma unroll
            for (int q = 0; q < 4; q++) acc[mt][nt][q] = 0.f;

    mma_w32x32((const unsigned*)As, (const unsigned*)Ws, mw, nw, grp, tig, acc);

    #pragma unroll
    for (int nt = 0; nt < 4; nt++) {
        const int col = nw * 32 + nt * 8 + tig * 2;
        const float2 bv = *(const float2*)(bias + col);
        #pragma unroll
        for (int mt = 0; mt < 2; mt++) {
            const int row = m0 + mw * 32 + mt * 16 + grp;
            float2 v0 = make_float2(acc[mt][nt][0] + bv.x, acc[mt][nt][1] + bv.y);
            float2 v1 = make_float2(acc[mt][nt][2] + bv.x, acc[mt][nt][3] + bv.y);
            if (RELU) {
                v0.x = fmaxf(v0.x, 0.f); v0.y = fmaxf(v0.y, 0.f);
                v1.x = fmaxf(v1.x, 0.f); v1.y = fmaxf(v1.y, 0.f);
            }
            if (ADDRES) {
                const float2 r0 = *(const float2*)(res + (size_t)row * C_ + col);
                const float2 r1 = *(const float2*)(res + (size_t)(row + 8) * C_ + col);
                v0.x += r0.x; v0.y += r0.y; v1.x += r1.x; v1.y += r1.y;
            }
            *(float2*)(out + (size_t)row * C_ + col) = v0;
            *(float2*)(out + (size_t)(row + 8) * C_ + col) = v1;
        }
    }
}

// =====================================================================
// Fused QKV: 128-token tiles, LN once, cp.async W pipelined across j
// =====================================================================
__global__ void __launch_bounds__(512) k_qkv3(
    const float* __restrict__ A,
    const float* __restrict__ wq, const float* __restrict__ bq, float* __restrict__ oq,
    const float* __restrict__ wk, const float* __restrict__ bk, float* __restrict__ ok,
    const float* __restrict__ wv, const float* __restrict__ bv, float* __restrict__ ov,
    const float* __restrict__ g, const float* __restrict__ bb)
{
    extern __shared__ float sm[];
    float* As = sm;
    float* Ws = sm + 128 * 132;
    const int tid = threadIdx.x;
    const int m0 = blockIdx.x * 128;
    const int warp = tid >> 5, lane = tid & 31;

    const float* Wj[3]   = {wq, wk, wv};
    const float* bj[3]   = {bq, bk, bv};
    float*       outj[3] = {oq, ok, ov};

    stage_W_async<512>(Wj[0], Ws, tid);
    CP_COMMIT();
    {
        const float4 gg = *(const float4*)(g  + lane * 4);
        const float4 gb = *(const float4*)(bb + lane * 4);
        for (int r = warp; r < 128; r += 16) {
            float4 v = *(const float4*)(A + (size_t)(m0 + r) * C_ + lane * 4);
            ln_row(v, gg, gb);
            uint4 u;
            u.x = cvt_tf32(v.x); u.y = cvt_tf32(v.y); u.z = cvt_tf32(v.z); u.w = cvt_tf32(v.w);
            *(uint4*)&As[r * 132 + lane * 4] = u;
        }
    }

    const int grp = lane >> 2, tig = lane & 3;
    const int mw = warp >> 2, nw = warp & 3;

    #pragma unroll 1
    for (int j = 0; j < 3; j++) {
        CP_WAIT0();
        __syncthreads();              // Ws[j] + As ready

        float acc[2][4][4];
        #pragma unroll
        for (int mt = 0; mt < 2; mt++)
            #pragma unroll
            for (int nt = 0; nt < 4; nt++)
                #pragma unroll
                for (int q = 0; q < 4; q++) acc[mt][nt][q] = 0.f;

        mma_w32x32((const unsigned*)As, (const unsigned*)Ws, mw, nw, grp, tig, acc);
        __syncthreads();              // all Ws reads done before overwrite

        if (j < 2) { stage_W_async<512>(Wj[j + 1], Ws, tid); CP_COMMIT(); }

        #pragma unroll
        for (int nt = 0; nt < 4; nt++) {
            const int col = nw * 32 + nt * 8 + tig * 2;
            const float2 bvv = *(const float2*)(bj[j] + col);
            #pragma unroll
            for (int mt = 0; mt < 2; mt++) {
                const int row = m0 + mw * 32 + mt * 16 + grp;
                float2 v0 = make_float2(acc[mt][nt][0] + bvv.x, acc[mt][nt][1] + bvv.y);
                float2 v1 = make_float2(acc[mt][nt][2] + bvv.x, acc[mt][nt][3] + bvv.y);
                *(float2*)(outj[j] + (size_t)row * C_ + col) = v0;
                *(float2*)(outj[j] + (size_t)(row + 8) * C_ + col) = v1;
            }
        }
    }
}

// ---------------- flash attention: double-buffered, hybrid MUFU/FMA exp ----------------
__global__ void __launch_bounds__(256) k_attn(
    const float* __restrict__ Q, const float* __restrict__ K,
    const float* __restrict__ V, const void* __restrict__ maskp,
    float* __restrict__ O)
{
    __shared__ __nv_bfloat16 Qs[128 * 24];
    __shared__ __nv_bfloat16 Ks[2][64 * 24];
    __shared__ __nv_bfloat16 Vs[2][64 * 24];
    __shared__ float msk[1024];
    const int tid = threadIdx.x;
    const int w = tid >> 5, l = tid & 31;
    const int grp = l >> 2, tig = l & 3;
    const int b = blockIdx.y >> 3, h = blockIdx.y & 7;
    const int q0 = blockIdx.x * 128;
    const int mint = g_mask_int;
    const int* mi = (const int*)maskp;
    const unsigned char* mu = (const unsigned char*)maskp;

    #pragma unroll
    for (int i = tid; i < 1024; i += 256) {
        const int mv = mint ? mi[b * L_ + i] : (int)mu[b * L_ + i];
        msk[i] = mv ? -1e30f : 0.f;
    }
    #pragma unroll
    for (int i = tid; i < 512; i += 256) {
        const int row = i >> 2, c4 = (i & 3) * 4;
        float4 f = *(const float4*)(Q + ((size_t)(b * L_ + q0 + row) * C_) + h * 16 + c4);
        __nv_bfloat162* dst = (__nv_bfloat162*)(Qs + row * 24 + c4);
        dst[0] = __floats2bfloat162_rn(f.x * 0.25f, f.y * 0.25f);
        dst[1] = __floats2bfloat162_rn(f.z * 0.25f, f.w * 0.25f);
    }

    const int krow = tid >> 2, kc4 = (tid & 3) * 4;
    {
        float4 fk = *(const float4*)(K + ((size_t)(b * L_ + krow) * C_) + h * 16 + kc4);
        float4 fv = *(const float4*)(V + ((size_t)(b * L_ + krow) * C_) + h * 16 + kc4);
        __nv_bfloat162* dk = (__nv_bfloat162*)(Ks[0] + krow * 24 + kc4);
        dk[0] = __floats2bfloat162_rn(fk.x, fk.y);
        dk[1] = __floats2bfloat162_rn(fk.z, fk.w);
        __nv_bfloat162* dv = (__nv_bfloat162*)(Vs[0] + krow * 24 + kc4);
        dv[0] = __floats2bfloat162_rn(fv.x, fv.y);
        dv[1] = __floats2bfloat162_rn(fv.z, fv.w);
    }
    __syncthreads();

    unsigned qa0, qa1, qa2, qa3;
    {
        const __nv_bfloat16* p = Qs + (w * 16 + (l & 15)) * 24 + ((l >> 4) * 8);
        unsigned ad = smem_u32(p);
        LDMX4(qa0, qa1, qa2, qa3, ad);
    }

    float o0[4] = {0,0,0,0}, o1[4] = {0,0,0,0};
    float sum0 = 0.f, sum1 = 0.f;

    for (int kt = 0; kt < 16; kt++) {
        const int buf = kt & 1;
        float4 fk, fv;
        if (kt < 15) {
            const size_t base = ((size_t)(b * L_ + (kt + 1) * 64 + krow) * C_) + h * 16 + kc4;
            fk = *(const float4*)(K + base);
            fv = *(const float4*)(V + base);
        }
        const int k0 = kt * 64;

        float s[8][4];
        #pragma unroll
        for (int ntp = 0; ntp < 4; ntp++) {
            const int nb = ntp * 16;
            const __nv_bfloat16* p = Ks[buf] + (nb + ((l >> 4) & 1) * 8 + (l & 7)) * 24 + ((l >> 3) & 1) * 8;
            unsigned ad = smem_u32(p);
            unsigned kb0, kb1, kb2, kb3;
            LDMX4(kb0, kb1, kb2, kb3, ad);
            MMA_BF16_Z(s[2*ntp],     qa0, qa1, qa2, qa3, kb0, kb1);
            MMA_BF16_Z(s[2*ntp + 1], qa0, qa1, qa2, qa3, kb2, kb3);
        }

        // hybrid exp: even tiles MUFU, odd tiles FMA-pipe polynomial
        unsigned pa[4][4];
        #pragma unroll
        for (int nt = 0; nt < 8; nt++) {
            const float2 mk = *(const float2*)&msk[k0 + nt * 8 + tig * 2];
            float p0, p1, p2, p3;
            if (nt & 1) {
                p0 = fexp(s[nt][0] + mk.x); p1 = fexp(s[nt][1] + mk.y);
                p2 = fexp(s[nt][2] + mk.x); p3 = fexp(s[nt][3] + mk.y);
            } else {
                p0 = __expf(s[nt][0] + mk.x); p1 = __expf(s[nt][1] + mk.y);
                p2 = __expf(s[nt][2] + mk.x); p3 = __expf(s[nt][3] + mk.y);
            }
            sum0 += p0 + p1; sum1 += p2 + p3;
            pa[nt >> 1][(nt & 1) * 2 + 0] = pack_bf16(p0, p1);
            pa[nt >> 1][(nt & 1) * 2 + 1] = pack_bf16(p2, p3);
        }

        #pragma unroll
        for (int kk = 0; kk < 4; kk++) {
            const __nv_bfloat16* p = Vs[buf] + (kk * 16 + ((l >> 3) & 1) * 8 + (l & 7)) * 24 + ((l >> 4) & 1) * 8;
            unsigned ad = smem_u32(p);
            unsigned vb0, vb1, vb2, vb3;
            LDMX4T(vb0, vb1, vb2, vb3, ad);
            MMA_BF16(o0, pa[kk][0], pa[kk][1], pa[kk][2], pa[kk][3], vb0, vb1);
            MMA_BF16(o1, pa[kk][0], pa[kk][1], pa[kk][2], pa[kk][3], vb2, vb3);
        }

        if (kt < 15) {
            __nv_bfloat162* dk = (__nv_bfloat162*)(Ks[buf ^ 1] + krow * 24 + kc4);
            dk[0] = __floats2bfloat162_rn(fk.x, fk.y);
            dk[1] = __floats2bfloat162_rn(fk.z, fk.w);
            __nv_bfloat162* dv = (__nv_bfloat162*)(Vs[buf ^ 1] + krow * 24 + kc4);
            dv[0] = __floats2bfloat162_rn(fv.x, fv.y);
            dv[1] = __floats2bfloat162_rn(fv.z, fv.w);
            __syncthreads();
        }
    }

    sum0 += __shfl_xor_sync(0xffffffffu, sum0, 1);
    sum0 += __shfl_xor_sync(0xffffffffu, sum0, 2);
    sum1 += __shfl_xor_sync(0xffffffffu, sum1, 1);
    sum1 += __shfl_xor_sync(0xffffffffu, sum1, 2);
    const float i0 = 1.f / sum0, i1 = 1.f / sum1;
    const int row0 = q0 + w * 16 + grp, row1 = row0 + 8;
    const int colb = h * 16 + tig * 2;
    *(float2*)(O + (size_t)(b * L_ + row0) * C_ + colb)     = make_float2(o0[0]*i0, o0[1]*i0);
    *(float2*)(O + (size_t)(b * L_ + row1) * C_ + colb)     = make_float2(o0[2]*i1, o0[3]*i1);
    *(float2*)(O + (size_t)(b * L_ + row0) * C_ + colb + 8) = make_float2(o1[0]*i0, o1[1]*i0);
    *(float2*)(O + (size_t)(b * L_ + row1) * C_ + colb + 8) = make_float2(o1[2]*i1, o1[3]*i1);
}

// ---------------- launcher ----------------
extern "C" void kernel_launch(void* const* d_in, const int* in_sizes, int n_in,
                              void* d_out, int out_size)
{
    const float* x    = (const float*)d_in[0];
    const void*  mask = d_in[1];
    const float* dw_w = (const float*)d_in[2];
    const float* pw_w = (const float*)d_in[3];
    const float* pw_b = (const float*)d_in[4];
    const float* ng   = (const float*)d_in[5];
    const float* nb   = (const float*)d_in[6];
    const float* wq = (const float*)d_in[7];   const float* bq = (const float*)d_in[8];
    const float* wk = (const float*)d_in[9];   const float* bk = (const float*)d_in[10];
    const float* wv = (const float*)d_in[11];  const float* bv = (const float*)d_in[12];
    const float* wo = (const float*)d_in[13];  const float* bo = (const float*)d_in[14];
    const float* w1 = (const float*)d_in[15];  const float* b1 = (const float*)d_in[16];
    const float* w2 = (const float*)d_in[17];  const float* b2 = (const float*)d_in[18];
    float* out = (float*)d_out;

    float *cur, *ln, *t1, *q, *k, *v;
    { void* p; cudaGetSymbolAddress(&p, g_cur); cur = (float*)p; }
    { void* p; cudaGetSymbolAddress(&p, g_ln);  ln  = (float*)p; }
    { void* p; cudaGetSymbolAddress(&p, g_t1);  t1  = (float*)p; }
    { void* p; cudaGetSymbolAddress(&p, g_q);   q   = (float*)p; }
    { void* p; cudaGetSymbolAddress(&p, g_k);   k   = (float*)p; }
    { void* p; cudaGetSymbolAddress(&p, g_v);   v   = (float*)p; }

    const int SMC = (70 * 132 + 128 * 132 + 896) * 4;   // 108128 B
    const int SMG = 2 * 128 * 132 * 4;                  // 135168 B
    cudaFuncSetAttribute(k_convblock, cudaFuncAttributeMaxDynamicSharedMemorySize, SMC);
    cudaFuncSetAttribute(k_qkv3, cudaFuncAttributeMaxDynamicSharedMemorySize, SMG);
    cudaFuncSetAttribute(k_gemm_tf32<false,false,true >, cudaFuncAttributeMaxDynamicSharedMemorySize, SMG);
    cudaFuncSetAttribute(k_gemm_tf32<true ,true ,false>, cudaFuncAttributeMaxDynamicSharedMemorySize, SMG);

    const dim3 tgrid(32, 4, 16), tblk(32, 8);

    k_in2work<<<tgrid, tblk>>>(x, cur, (const unsigned char*)mask);

    const float* cin[4]  = {cur, t1, cur, t1};
    float*       cout[4] = {t1, cur, t1, cur};
    for (int i = 0; i < NCONV_; i++) {
        k_convblock<<<256, 512, SMC>>>(cin[i], dw_w + i * C_ * 7, pw_w + i * C_ * C_,
                                       pw_b + i * C_, ng + i * C_, nb + i * C_, cout[i]);
    }

    k_qkv3<<<128, 512, SMG>>>(cur, wq, bq, q, wk, bk, k, wv, bv, v,
                              ng + NCONV_ * C_, nb + NCONV_ * C_);
    k_attn<<<dim3(8, 128), 256>>>(q, k, v, mask, ln);
    k_gemm_tf32<false,false,true ><<<128, 512, SMG>>>(ln, wo, bo, cur, cur, nullptr, nullptr);

    k_gemm_tf32<true ,true ,false><<<128, 512, SMG>>>(cur, w1, b1, nullptr, t1,
                                                      ng + (NCONV_ + 1) * C_, nb + (NCONV_ + 1) * C_);
    k_gemm_tf32<false,false,true ><<<128, 512, SMG>>>(t1, w2, b2, cur, cur, nullptr, nullptr);

    k_work2out<<<tgrid, tblk>>>(cur, out);
}

// round 16
// speedup vs baseline: 1.1029x; 1.1029x over previous
#include <cuda_runtime.h>
#include <cuda_bf16.h>
#include <math.h>

#define B_ 16
#define C_ 128
#define L_ 1024
#define H_ 8
#define DK_ 16
#define NCONV_ 4
#define NTOK (B_*L_)
#define NELEM (B_*L_*C_)

// ---------------- scratch ----------------
__device__ float g_cur[NELEM];
__device__ float g_ln[NELEM];
__device__ float g_t1[NELEM];
__device__ float g_q[NELEM];
__device__ float g_k[NELEM];
__device__ float g_v[NELEM];
__device__ int   g_mask_int;

// ---------------- asm helpers ----------------
#define LDMX4(r0,r1,r2,r3,addr) \
  asm volatile("ldmatrix.sync.aligned.m8n8.x4.shared.b16 {%0,%1,%2,%3},[%4];" \
    : "=r"(r0),"=r"(r1),"=r"(r2),"=r"(r3) : "r"(addr))

#define LDMX4T(r0,r1,r2,r3,addr) \
  asm volatile("ldmatrix.sync.aligned.m8n8.x4.trans.shared.b16 {%0,%1,%2,%3},[%4];" \
    : "=r"(r0),"=r"(r1),"=r"(r2),"=r"(r3) : "r"(addr))

#define MMA_BF16_Z(d,a0,a1,a2,a3,b0,b1) \
  asm volatile("mma.sync.aligned.m16n8k16.row.col.f32.bf16.bf16.f32 " \
    "{%0,%1,%2,%3},{%4,%5,%6,%7},{%8,%9},{%10,%11,%12,%13};" \
    : "=f"(d[0]),"=f"(d[1]),"=f"(d[2]),"=f"(d[3]) \
    : "r"(a0),"r"(a1),"r"(a2),"r"(a3),"r"(b0),"r"(b1), \
      "f"(0.f),"f"(0.f),"f"(0.f),"f"(0.f))

#define MMA_BF16(d,a0,a1,a2,a3,b0,b1) \
  asm volatile("mma.sync.aligned.m16n8k16.row.col.f32.bf16.bf16.f32 " \
    "{%0,%1,%2,%3},{%4,%5,%6,%7},{%8,%9},{%0,%1,%2,%3};" \
    : "+f"(d[0]),"+f"(d[1]),"+f"(d[2]),"+f"(d[3]) \
    : "r"(a0),"r"(a1),"r"(a2),"r"(a3),"r"(b0),"r"(b1))

#define MMA_TF32(d,a,b) \
  asm volatile("mma.sync.aligned.m16n8k8.row.col.f32.tf32.tf32.f32 " \
    "{%0,%1,%2,%3},{%4,%5,%6,%7},{%8,%9},{%0,%1,%2,%3};" \
    : "+f"(d[0]),"+f"(d[1]),"+f"(d[2]),"+f"(d[3]) \
    : "r"((a)[0]),"r"((a)[1]),"r"((a)[2]),"r"((a)[3]),"r"((b)[0]),"r"((b)[1]))

#define CP_ASYNC16(saddr, gptr) \
  asm volatile("cp.async.ca.shared.global [%0],[%1],16;" :: "r"(saddr), "l"(gptr))
#define CP_COMMIT() asm volatile("cp.async.commit_group;")
#define CP_WAIT0()  asm volatile("cp.async.wait_group 0;")

__device__ __forceinline__ unsigned cvt_tf32(float f) {
    unsigned u; asm("cvt.rna.tf32.f32 %0,%1;" : "=r"(u) : "f"(f)); return u;
}
__device__ __forceinline__ unsigned pack_bf16(float a, float b) {
    __nv_bfloat162 t = __floats2bfloat162_rn(a, b);
    return *(unsigned*)&t;
}
__device__ __forceinline__ unsigned smem_u32(const void* p) {
    return (unsigned)__cvta_generic_to_shared(p);
}

__device__ __forceinline__ void ln_row(float4& v, const float4& gg, const float4& gb) {
    float s  = v.x + v.y + v.z + v.w;
    float sq = v.x*v.x + v.y*v.y + v.z*v.z + v.w*v.w;
    #pragma unroll
    for (int off = 16; off; off >>= 1) {
        s  += __shfl_xor_sync(0xffffffffu, s,  off);
        sq += __shfl_xor_sync(0xffffffffu, sq, off);
    }
    const float mean = s * (1.f/128.f);
    const float var  = sq * (1.f/128.f) - mean * mean;
    const float r    = rsqrtf(var + 1e-5f);
    v.x = (v.x - mean) * r * gg.x + gb.x;
    v.y = (v.y - mean) * r * gg.y + gb.y;
    v.z = (v.z - mean) * r * gg.z + gb.z;
    v.w = (v.w - mean) * r * gg.w + gb.w;
}

// async-stage [128][128] fp32 -> smem [128][132] raw bits (tf32 via HW trunc)
template<int NT>
__device__ __forceinline__ void stage_W_async(const float* __restrict__ W, float* Ws, int tid) {
    #pragma unroll
    for (int i = 0; i < 4096 / NT; i++) {
        const int f4 = tid + i * NT;
        const int row = f4 >> 5, c = (f4 & 31) * 4;
        CP_ASYNC16(smem_u32(&Ws[row * 132 + c]), W + (size_t)row * C_ + c);
    }
}

// 64x128x128 MMA, 16 warps, warp tile 16x32 (mw=warp>>2 rows, nw=warp&3 cols)
__device__ __forceinline__ void mma_64x128(
    const unsigned* Au, const unsigned* Wu, int mw, int nw, int grp, int tig,
    float acc[4][4])
{
    const int r = mw * 16 + grp;
    #pragma unroll
    for (int ks = 0; ks < 16; ks++) {
        const int kb = ks * 8;
        unsigned af[4], bf[4][2];
        af[0] = Au[r * 132 + kb + tig];
        af[1] = Au[(r + 8) * 132 + kb + tig];
        af[2] = Au[r * 132 + kb + tig + 4];
        af[3] = Au[(r + 8) * 132 + kb + tig + 4];
        #pragma unroll
        for (int nt = 0; nt < 4; nt++) {
            const int rr = nw * 32 + nt * 8 + grp;
            bf[nt][0] = Wu[rr * 132 + kb + tig];
            bf[nt][1] = Wu[rr * 132 + kb + tig + 4];
        }
        #pragma unroll
        for (int nt = 0; nt < 4; nt++)
            MMA_TF32(acc[nt], af, bf[nt]);
    }
}

// 128x128x128 MMA (16 warps, warp tile 32x32): acc[2][4][4]
__device__ __forceinline__ void mma_w32x32(
    const unsigned* Au, const unsigned* Wu, int mw, int nw, int grp, int tig,
    float acc[2][4][4])
{
    #pragma unroll
    for (int ks = 0; ks < 16; ks++) {
        const int kb = ks * 8;
        unsigned af[2][4], bf[4][2];
        #pragma unroll
        for (int mt = 0; mt < 2; mt++) {
            const int r = mw * 32 + mt * 16 + grp;
            af[mt][0] = Au[r * 132 + kb + tig];
            af[mt][1] = Au[(r + 8) * 132 + kb + tig];
            af[mt][2] = Au[r * 132 + kb + tig + 4];
            af[mt][3] = Au[(r + 8) * 132 + kb + tig + 4];
        }
        #pragma unroll
        for (int nt = 0; nt < 4; nt++) {
            const int r = nw * 32 + nt * 8 + grp;
            bf[nt][0] = Wu[r * 132 + kb + tig];
            bf[nt][1] = Wu[r * 132 + kb + tig + 4];
        }
        #pragma unroll
        for (int mt = 0; mt < 2; mt++)
            #pragma unroll
            for (int nt = 0; nt < 4; nt++)
                MMA_TF32(acc[mt][nt], af[mt], bf[nt]);
    }
}

// ---------------- [B,C,L] -> [B,L,C] + pos encoding (+ mask detect in block 0) ----------------
__global__ void k_in2work(const float* __restrict__ x, float* __restrict__ out,
                          const unsigned char* __restrict__ m) {
    __shared__ float tile[32][33];
    __shared__ int sdet;
    const int b  = blockIdx.z;
    const int l0 = blockIdx.x * 32;
    const int c0 = blockIdx.y * 32;
    const int tx = threadIdx.x, ty = threadIdx.y;
    const int tid = ty * 32 + tx;
    const bool det = (blockIdx.x == 0 && blockIdx.y == 0 && blockIdx.z == 0);
    if (det) {
        if (tid == 0) sdet = 0;
        __syncthreads();
        int nz = 0;
        for (int i = tid; i < NTOK; i += 256)
            if ((i & 3) && m[i]) nz = 1;
        if (nz) atomicOr(&sdet, 1);
        __syncthreads();
        if (tid == 0) g_mask_int = (sdet == 0) ? 1 : 0;
    }
    #pragma unroll
    for (int j = 0; j < 4; j++)
        tile[ty + 8*j][tx] = x[((size_t)b*C_ + (c0 + ty + 8*j))*L_ + l0 + tx];
    __syncthreads();
    const int c = c0 + tx;
    const float fi = (float)c;
    float freq, phase;
    if (c & 1) { freq = -powf(10000.f, (1.f - fi) * (1.f/128.f)); phase = 1.57079632679489662f; }
    else       { freq =  powf(10000.f, -fi * (1.f/128.f));        phase = 0.f; }
    #pragma unroll
    for (int j = 0; j < 4; j++) {
        const int l = l0 + ty + 8*j;
        out[((size_t)b*L_ + l)*C_ + c] = tile[tx][ty + 8*j] + sinf((float)l * freq + phase);
    }
}

// ---------------- [B,L,C] -> [B,C,L] ----------------
__global__ void k_work2out(const float* __restrict__ in, float* __restrict__ out) {
    __shared__ float tile[32][33];
    const int b  = blockIdx.z;
    const int l0 = blockIdx.x * 32;
    const int c0 = blockIdx.y * 32;
    const int tx = threadIdx.x, ty = threadIdx.y;
    #pragma unroll
    for (int j = 0; j < 4; j++)
        tile[ty + 8*j][tx] = in[((size_t)b*L_ + (l0 + ty + 8*j))*C_ + c0 + tx];
    __syncthreads();
    #pragma unroll
    for (int j = 0; j < 4; j++)
        out[((size_t)b*C_ + (c0 + ty + 8*j))*L_ + l0 + tx] = tile[tx][ty + 8*j];
}

// =====================================================================
// Fused conv block (R13 winner, FROZEN)
// =====================================================================
__global__ void __launch_bounds__(512, 2) k_convblock(
    const float* __restrict__ in, const float* __restrict__ dw,
    const float* __restrict__ pw, const float* __restrict__ pb,
    const float* __restrict__ g,  const float* __restrict__ bb,
    float* __restrict__ out)
{
    extern __shared__ float sm[];
    float* y   = sm;                       // [70][132]; rows 0..63 become As
    float* Ws  = y  + 70 * 132;            // [128][132] raw fp32
    float* dwT = Ws + 128 * 132;           // [7][128]
    const int tid = threadIdx.x;
    const int b  = blockIdx.x >> 4;
    const int l0 = (blockIdx.x & 15) * 64;
    const int warp = tid >> 5, lane = tid & 31;

    stage_W_async<512>(pw, Ws, tid);
    CP_COMMIT();
    for (int i = tid; i < 896; i += 512) {
        const int k = i >> 7, c = i & 127;
        dwT[i] = dw[c * 7 + k];
    }
    {
        const float4 gg = *(const float4*)(g  + lane * 4);
        const float4 gb = *(const float4*)(bb + lane * 4);
        for (int r = warp; r < 70; r += 16) {
            const int l = l0 - 3 + r;
            float4 v = make_float4(0.f, 0.f, 0.f, 0.f);
            if (l >= 0 && l < L_) {
                v = *(const float4*)(in + ((size_t)(b * L_ + l)) * C_ + lane * 4);
                ln_row(v, gg, gb);
            } else {
                ln_row(v, gg, gb);   // keep warp converged
                v = make_float4(0.f, 0.f, 0.f, 0.f);
            }
            *(float4*)&y[r * 132 + lane * 4] = v;
        }
    }
    CP_WAIT0();
    __syncthreads();

    uint2 racc[8];
    {
        const int p  = tid & 63;
        const int lb = (tid >> 6) * 8;
        const int cb = p * 2;
        float2 wk[7];
        #pragma unroll
        for (int k = 0; k < 7; k++) wk[k] = *(const float2*)&dwT[k * 128 + cb];
        float2 w0 = *(const float2*)&y[(lb + 0) * 132 + cb];
        float2 w1 = *(const float2*)&y[(lb + 1) * 132 + cb];
        float2 w2 = *(const float2*)&y[(lb + 2) * 132 + cb];
        float2 w3 = *(const float2*)&y[(lb + 3) * 132 + cb];
        float2 w4 = *(const float2*)&y[(lb + 4) * 132 + cb];
        float2 w5 = *(const float2*)&y[(lb + 5) * 132 + cb];
        #pragma unroll
        for (int i = 0; i < 8; i++) {
            const float2 w6 = *(const float2*)&y[(lb + i + 6) * 132 + cb];
            float ax = wk[0].x * w0.x + wk[1].x * w1.x + wk[2].x * w2.x
                     + wk[3].x * w3.x + wk[4].x * w4.x + wk[5].x * w5.x
                     + wk[6].x * w6.x;
            float ay = wk[0].y * w0.y + wk[1].y * w1.y + wk[2].y * w2.y
                     + wk[3].y * w3.y + wk[4].y * w4.y + wk[5].y * w5.y
                     + wk[6].y * w6.y;
            racc[i].x = cvt_tf32(ax);
            racc[i].y = cvt_tf32(ay);
            w0 = w1; w1 = w2; w2 = w3; w3 = w4; w4 = w5; w5 = w6;
        }
    }
    __syncthreads();
    {
        const int p  = tid & 63;
        const int lb = (tid >> 6) * 8;
        const int cb = p * 2;
        #pragma unroll
        for (int i = 0; i < 8; i++)
            *(uint2*)&y[(lb + i) * 132 + cb] = racc[i];
    }
    __syncthreads();

    const int grp = lane >> 2, tig = lane & 3;
    const int mw = warp >> 2, nw = warp & 3;
    float acc[4][4];
    #pragma unroll
    for (int nt = 0; nt < 4; nt++)
        #pragma unroll
        for (int q = 0; q < 4; q++) acc[nt][q] = 0.f;

    mma_64x128((const unsigned*)y, (const unsigned*)Ws, mw, nw, grp, tig, acc);

    #pragma unroll
    for (int nt = 0; nt < 4; nt++) {
        const int col = nw * 32 + nt * 8 + tig * 2;
        const float2 bv = *(const float2*)(pb + col);
        const int rl = mw * 16 + grp;
        const size_t r0 = (size_t)(b * L_ + l0 + rl) * C_ + col;
        const size_t r1 = (size_t)(b * L_ + l0 + rl + 8) * C_ + col;
        float2 v0 = make_float2(fmaxf(acc[nt][0] + bv.x, 0.f), fmaxf(acc[nt][1] + bv.y, 0.f));
        float2 v1 = make_float2(fmaxf(acc[nt][2] + bv.x, 0.f), fmaxf(acc[nt][3] + bv.y, 0.f));
        const float2 q0 = *(const float2*)(in + r0);
        const float2 q1 = *(const float2*)(in + r1);
        v0.x += q0.x; v0.y += q0.y; v1.x += q1.x; v1.y += q1.y;
        *(float2*)(out + r0) = v0;
        *(float2*)(out + r1) = v1;
    }
}

// =====================================================================
// tf32 GEMM, 128-token tiles, cp.async staging
// =====================================================================
template<bool LNA, bool RELU, bool ADDRES>
__global__ void __launch_bounds__(512) k_gemm_tf32(
    const float* __restrict__ A, const float* __restrict__ W,
    const float* __restrict__ bias, const float* __restrict__ res,
    float* __restrict__ out,
    const float* __restrict__ g, const float* __restrict__ bb)
{
    extern __shared__ float sm[];
    float* As = sm;                        // [128][132]
    float* Ws = sm + 128 * 132;            // [128][132]
    const int tid = threadIdx.x;
    const int m0 = blockIdx.x * 128;
    const int warp = tid >> 5, lane = tid & 31;

    stage_W_async<512>(W, Ws, tid);
    if (LNA) {
        CP_COMMIT();
        const float4 gg = *(const float4*)(g  + lane * 4);
        const float4 gb = *(const float4*)(bb + lane * 4);
        for (int r = warp; r < 128; r += 16) {
            float4 v = *(const float4*)(A + (size_t)(m0 + r) * C_ + lane * 4);
            ln_row(v, gg, gb);
            uint4 u;
            u.x = cvt_tf32(v.x); u.y = cvt_tf32(v.y); u.z = cvt_tf32(v.z); u.w = cvt_tf32(v.w);
            *(uint4*)&As[r * 132 + lane * 4] = u;
        }
    } else {
        #pragma unroll
        for (int i = 0; i < 8; i++) {
            const int f4 = tid + i * 512;
            const int row = f4 >> 5, c = (f4 & 31) * 4;
            CP_ASYNC16(smem_u32(&As[row * 132 + c]), A + (size_t)(m0 + row) * C_ + c);
        }
        CP_COMMIT();
    }
    CP_WAIT0();
    __syncthreads();

    const int grp = lane >> 2, tig = lane & 3;
    const int mw = warp >> 2, nw = warp & 3;
    float acc[2][4][4];
    #pragma unroll
    for (int mt = 0; mt < 2; mt++)
        #pragma unroll
        for (int nt = 0; nt < 4; nt++)
            #pragma unroll
            for (int q = 0; q < 4; q++) acc[mt][nt][q] = 0.f;

    mma_w32x32((const unsigned*)As, (const unsigned*)Ws, mw, nw, grp, tig, acc);

    #pragma unroll
    for (int nt = 0; nt < 4; nt++) {
        const int col = nw * 32 + nt * 8 + tig * 2;
        const float2 bv = *(const float2*)(bias + col);
        #pragma unroll
        for (int mt = 0; mt < 2; mt++) {
            const int row = m0 + mw * 32 + mt * 16 + grp;
            float2 v0 = make_float2(acc[mt][nt][0] + bv.x, acc[mt][nt][1] + bv.y);
            float2 v1 = make_float2(acc[mt][nt][2] + bv.x, acc[mt][nt][3] + bv.y);
            if (RELU) {
                v0.x = fmaxf(v0.x, 0.f); v0.y = fmaxf(v0.y, 0.f);
                v1.x = fmaxf(v1.x, 0.f); v1.y = fmaxf(v1.y, 0.f);
            }
            if (ADDRES) {
                const float2 r0 = *(const float2*)(res + (size_t)row * C_ + col);
                const float2 r1 = *(const float2*)(res + (size_t)(row + 8) * C_ + col);
                v0.x += r0.x; v0.y += r0.y; v1.x += r1.x; v1.y += r1.y;
            }
            *(float2*)(out + (size_t)row * C_ + col) = v0;
            *(float2*)(out + (size_t)(row + 8) * C_ + col) = v1;
        }
    }
}

// =====================================================================
// Fused QKV: 128-token tiles, LN once, cp.async W pipelined across j
// =====================================================================
__global__ void __launch_bounds__(512) k_qkv3(
    const float* __restrict__ A,
    const float* __restrict__ wq, const float* __restrict__ bq, float* __restrict__ oq,
    const float* __restrict__ wk, const float* __restrict__ bk, float* __restrict__ ok,
    const float* __restrict__ wv, const float* __restrict__ bv, float* __restrict__ ov,
    const float* __restrict__ g, const float* __restrict__ bb)
{
    extern __shared__ float sm[];
    float* As = sm;
    float* Ws = sm + 128 * 132;
    const int tid = threadIdx.x;
    const int m0 = blockIdx.x * 128;
    const int warp = tid >> 5, lane = tid & 31;

    const float* Wj[3]   = {wq, wk, wv};
    const float* bj[3]   = {bq, bk, bv};
    float*       outj[3] = {oq, ok, ov};

    stage_W_async<512>(Wj[0], Ws, tid);
    CP_COMMIT();
    {
        const float4 gg = *(const float4*)(g  + lane * 4);
        const float4 gb = *(const float4*)(bb + lane * 4);
        for (int r = warp; r < 128; r += 16) {
            float4 v = *(const float4*)(A + (size_t)(m0 + r) * C_ + lane * 4);
            ln_row(v, gg, gb);
            uint4 u;
            u.x = cvt_tf32(v.x); u.y = cvt_tf32(v.y); u.z = cvt_tf32(v.z); u.w = cvt_tf32(v.w);
            *(uint4*)&As[r * 132 + lane * 4] = u;
        }
    }

    const int grp = lane >> 2, tig = lane & 3;
    const int mw = warp >> 2, nw = warp & 3;

    #pragma unroll 1
    for (int j = 0; j < 3; j++) {
        CP_WAIT0();
        __syncthreads();              // Ws[j] + As ready

        float acc[2][4][4];
        #pragma unroll
        for (int mt = 0; mt < 2; mt++)
            #pragma unroll
            for (int nt = 0; nt < 4; nt++)
                #pragma unroll
                for (int q = 0; q < 4; q++) acc[mt][nt][q] = 0.f;

        mma_w32x32((const unsigned*)As, (const unsigned*)Ws, mw, nw, grp, tig, acc);
        __syncthreads();              // all Ws reads done before overwrite

        if (j < 2) { stage_W_async<512>(Wj[j + 1], Ws, tid); CP_COMMIT(); }

        #pragma unroll
        for (int nt = 0; nt < 4; nt++) {
            const int col = nw * 32 + nt * 8 + tig * 2;
            const float2 bvv = *(const float2*)(bj[j] + col);
            #pragma unroll
            for (int mt = 0; mt < 2; mt++) {
                const int row = m0 + mw * 32 + mt * 16 + grp;
                float2 v0 = make_float2(acc[mt][nt][0] + bvv.x, acc[mt][nt][1] + bvv.y);
                float2 v1 = make_float2(acc[mt][nt][2] + bvv.x, acc[mt][nt][3] + bvv.y);
                *(float2*)(outj[j] + (size_t)row * C_ + col) = v0;
                *(float2*)(outj[j] + (size_t)(row + 8) * C_ + col) = v1;
            }
        }
    }
}

// ---------------- flash attention: double-buffered, MMA row sums ----------------
__global__ void __launch_bounds__(256) k_attn(
    const float* __restrict__ Q, const float* __restrict__ K,
    const float* __restrict__ V, const void* __restrict__ maskp,
    float* __restrict__ O)
{
    __shared__ __nv_bfloat16 Qs[128 * 24];
    __shared__ __nv_bfloat16 Ks[2][64 * 24];
    __shared__ __nv_bfloat16 Vs[2][64 * 24];
    __shared__ float msk[1024];
    const int tid = threadIdx.x;
    const int w = tid >> 5, l = tid & 31;
    const int grp = l >> 2, tig = l & 3;
    const int b = blockIdx.y >> 3, h = blockIdx.y & 7;
    const int q0 = blockIdx.x * 128;
    const int mint = g_mask_int;
    const int* mi = (const int*)maskp;
    const unsigned char* mu = (const unsigned char*)maskp;
    const unsigned ONES = 0x3F803F80u;   // bf16 {1.0, 1.0}

    #pragma unroll
    for (int i = tid; i < 1024; i += 256) {
        const int mv = mint ? mi[b * L_ + i] : (int)mu[b * L_ + i];
        msk[i] = mv ? -1e30f : 0.f;
    }
    #pragma unroll
    for (int i = tid; i < 512; i += 256) {
        const int row = i >> 2, c4 = (i & 3) * 4;
        float4 f = *(const float4*)(Q + ((size_t)(b * L_ + q0 + row) * C_) + h * 16 + c4);
        __nv_bfloat162* dst = (__nv_bfloat162*)(Qs + row * 24 + c4);
        dst[0] = __floats2bfloat162_rn(f.x * 0.25f, f.y * 0.25f);
        dst[1] = __floats2bfloat162_rn(f.z * 0.25f, f.w * 0.25f);
    }

    const int krow = tid >> 2, kc4 = (tid & 3) * 4;
    {
        float4 fk = *(const float4*)(K + ((size_t)(b * L_ + krow) * C_) + h * 16 + kc4);
        float4 fv = *(const float4*)(V + ((size_t)(b * L_ + krow) * C_) + h * 16 + kc4);
        __nv_bfloat162* dk = (__nv_bfloat162*)(Ks[0] + krow * 24 + kc4);
        dk[0] = __floats2bfloat162_rn(fk.x, fk.y);
        dk[1] = __floats2bfloat162_rn(fk.z, fk.w);
        __nv_bfloat162* dv = (__nv_bfloat162*)(Vs[0] + krow * 24 + kc4);
        dv[0] = __floats2bfloat162_rn(fv.x, fv.y);
        dv[1] = __floats2bfloat162_rn(fv.z, fv.w);
    }
    __syncthreads();

    unsigned qa0, qa1, qa2, qa3;
    {
        const __nv_bfloat16* p = Qs + (w * 16 + (l & 15)) * 24 + ((l >> 4) * 8);
        unsigned ad = smem_u32(p);
        LDMX4(qa0, qa1, qa2, qa3, ad);
    }

    float o0[4] = {0,0,0,0}, o1[4] = {0,0,0,0};
    float sacc[4] = {0,0,0,0};   // MMA row sums: [0]=row grp, [2]=row grp+8

    for (int kt = 0; kt < 16; kt++) {
        const int buf = kt & 1;
        float4 fk, fv;
        if (kt < 15) {
            const size_t base = ((size_t)(b * L_ + (kt + 1) * 64 + krow) * C_) + h * 16 + kc4;
            fk = *(const float4*)(K + base);
            fv = *(const float4*)(V + base);
        }
        const int k0 = kt * 64;

        float s[8][4];
        #pragma unroll
        for (int ntp = 0; ntp < 4; ntp++) {
            const int nb = ntp * 16;
            const __nv_bfloat16* p = Ks[buf] + (nb + ((l >> 4) & 1) * 8 + (l & 7)) * 24 + ((l >> 3) & 1) * 8;
            unsigned ad = smem_u32(p);
            unsigned kb0, kb1, kb2, kb3;
            LDMX4(kb0, kb1, kb2, kb3, ad);
            MMA_BF16_Z(s[2*ntp],     qa0, qa1, qa2, qa3, kb0, kb1);
            MMA_BF16_Z(s[2*ntp + 1], qa0, qa1, qa2, qa3, kb2, kb3);
        }

        unsigned pa[4][4];
        #pragma unroll
        for (int nt = 0; nt < 8; nt++) {
            const float2 mk = *(const float2*)&msk[k0 + nt * 8 + tig * 2];
            const float p0 = __expf(s[nt][0] + mk.x), p1 = __expf(s[nt][1] + mk.y);
            const float p2 = __expf(s[nt][2] + mk.x), p3 = __expf(s[nt][3] + mk.y);
            pa[nt >> 1][(nt & 1) * 2 + 0] = pack_bf16(p0, p1);
            pa[nt >> 1][(nt & 1) * 2 + 1] = pack_bf16(p2, p3);
        }

        #pragma unroll
        for (int kk = 0; kk < 4; kk++) {
            const __nv_bfloat16* p = Vs[buf] + (kk * 16 + ((l >> 3) & 1) * 8 + (l & 7)) * 24 + ((l >> 4) & 1) * 8;
            unsigned ad = smem_u32(p);
            unsigned vb0, vb1, vb2, vb3;
            LDMX4T(vb0, vb1, vb2, vb3, ad);
            MMA_BF16(o0, pa[kk][0], pa[kk][1], pa[kk][2], pa[kk][3], vb0, vb1);
            MMA_BF16(o1, pa[kk][0], pa[kk][1], pa[kk][2], pa[kk][3], vb2, vb3);
            // row sums on the tensor pipe: P(16x16) x ones(16x8)
            MMA_BF16(sacc, pa[kk][0], pa[kk][1], pa[kk][2], pa[kk][3], ONES, ONES);
        }

        if (kt < 15) {
            __nv_bfloat162* dk = (__nv_bfloat162*)(Ks[buf ^ 1] + krow * 24 + kc4);
            dk[0] = __floats2bfloat162_rn(fk.x, fk.y);
            dk[1] = __floats2bfloat162_rn(fk.z, fk.w);
            __nv_bfloat162* dv = (__nv_bfloat162*)(Vs[buf ^ 1] + krow * 24 + kc4);
            dv[0] = __floats2bfloat162_rn(fv.x, fv.y);
            dv[1] = __floats2bfloat162_rn(fv.z, fv.w);
            __syncthreads();
        }
    }

    const float i0 = 1.f / sacc[0], i1 = 1.f / sacc[2];
    const int row0 = q0 + w * 16 + grp, row1 = row0 + 8;
    const int colb = h * 16 + tig * 2;
    *(float2*)(O + (size_t)(b * L_ + row0) * C_ + colb)     = make_float2(o0[0]*i0, o0[1]*i0);
    *(float2*)(O + (size_t)(b * L_ + row1) * C_ + colb)     = make_float2(o0[2]*i1, o0[3]*i1);
    *(float2*)(O + (size_t)(b * L_ + row0) * C_ + colb + 8) = make_float2(o1[0]*i0, o1[1]*i0);
    *(float2*)(O + (size_t)(b * L_ + row1) * C_ + colb + 8) = make_float2(o1[2]*i1, o1[3]*i1);
}

// ---------------- launcher ----------------
extern "C" void kernel_launch(void* const* d_in, const int* in_sizes, int n_in,
                              void* d_out, int out_size)
{
    const float* x    = (const float*)d_in[0];
    const void*  mask = d_in[1];
    const float* dw_w = (const float*)d_in[2];
    const float* pw_w = (const float*)d_in[3];
    const float* pw_b = (const float*)d_in[4];
    const float* ng   = (const float*)d_in[5];
    const float* nb   = (const float*)d_in[6];
    const float* wq = (const float*)d_in[7];   const float* bq = (const float*)d_in[8];
    const float* wk = (const float*)d_in[9];   const float* bk = (const float*)d_in[10];
    const float* wv = (const float*)d_in[11];  const float* bv = (const float*)d_in[12];
    const float* wo = (const float*)d_in[13];  const float* bo = (const float*)d_in[14];
    const float* w1 = (const float*)d_in[15];  const float* b1 = (const float*)d_in[16];
    const float* w2 = (const float*)d_in[17];  const float* b2 = (const float*)d_in[18];
    float* out = (float*)d_out;

    float *cur, *ln, *t1, *q, *k, *v;
    { void* p; cudaGetSymbolAddress(&p, g_cur); cur = (float*)p; }
    { void* p; cudaGetSymbolAddress(&p, g_ln);  ln  = (float*)p; }
    { void* p; cudaGetSymbolAddress(&p, g_t1);  t1  = (float*)p; }
    { void* p; cudaGetSymbolAddress(&p, g_q);   q   = (float*)p; }
    { void* p; cudaGetSymbolAddress(&p, g_k);   k   = (float*)p; }
    { void* p; cudaGetSymbolAddress(&p, g_v);   v   = (float*)p; }

    const int SMC = (70 * 132 + 128 * 132 + 896) * 4;   // 108128 B
    const int SMG = 2 * 128 * 132 * 4;                  // 135168 B
    cudaFuncSetAttribute(k_convblock, cudaFuncAttributeMaxDynamicSharedMemorySize, SMC);
    cudaFuncSetAttribute(k_qkv3, cudaFuncAttributeMaxDynamicSharedMemorySize, SMG);
    cudaFuncSetAttribute(k_gemm_tf32<false,false,true >, cudaFuncAttributeMaxDynamicSharedMemorySize, SMG);
    cudaFuncSetAttribute(k_gemm_tf32<true ,true ,false>, cudaFuncAttributeMaxDynamicSharedMemorySize, SMG);

    const dim3 tgrid(32, 4, 16), tblk(32, 8);

    k_in2work<<<tgrid, tblk>>>(x, cur, (const unsigned char*)mask);

    const float* cin[4]  = {cur, t1, cur, t1};
    float*       cout[4] = {t1, cur, t1, cur};
    for (int i = 0; i < NCONV_; i++) {
        k_convblock<<<256, 512, SMC>>>(cin[i], dw_w + i * C_ * 7, pw_w + i * C_ * C_,
                                       pw_b + i * C_, ng + i * C_, nb + i * C_, cout[i]);
    }

    k_qkv3<<<128, 512, SMG>>>(cur, wq, bq, q, wk, bk, k, wv, bv, v,
                              ng + NCONV_ * C_, nb + NCONV_ * C_);
    k_attn<<<dim3(8, 128), 256>>>(q, k, v, mask, ln);
    k_gemm_tf32<false,false,true ><<<128, 512, SMG>>>(ln, wo, bo, cur, cur, nullptr, nullptr);

    k_gemm_tf32<true ,true ,false><<<128, 512, SMG>>>(cur, w1, b1, nullptr, t1,
                                                      ng + (NCONV_ + 1) * C_, nb + (NCONV_ + 1) * C_);
    k_gemm_tf32<false,false,true ><<<128, 512, SMG>>>(t1, w2, b2, cur, cur, nullptr, nullptr);

    k_work2out<<<tgrid, tblk>>>(cur, out);
}

// round 17
// speedup vs baseline: 1.1480x; 1.0409x over previous
#include <cuda_runtime.h>
#include <cuda_bf16.h>
#include <math.h>

#define B_ 16
#define C_ 128
#define L_ 1024
#define H_ 8
#define DK_ 16
#define NCONV_ 4
#define NTOK (B_*L_)
#define NELEM (B_*L_*C_)

// ---------------- scratch ----------------
__device__ float g_cur[NELEM];
__device__ float g_ln[NELEM];
__device__ float g_t1[NELEM];
__device__ float g_q[NELEM];
__device__ float g_k[NELEM];
__device__ float g_v[NELEM];
__device__ int   g_mask_int;

// ---------------- asm helpers ----------------
#define LDMX4(r0,r1,r2,r3,addr) \
  asm volatile("ldmatrix.sync.aligned.m8n8.x4.shared.b16 {%0,%1,%2,%3},[%4];" \
    : "=r"(r0),"=r"(r1),"=r"(r2),"=r"(r3) : "r"(addr))

#define LDMX4T(r0,r1,r2,r3,addr) \
  asm volatile("ldmatrix.sync.aligned.m8n8.x4.trans.shared.b16 {%0,%1,%2,%3},[%4];" \
    : "=r"(r0),"=r"(r1),"=r"(r2),"=r"(r3) : "r"(addr))

#define MMA_BF16_Z(d,a0,a1,a2,a3,b0,b1) \
  asm volatile("mma.sync.aligned.m16n8k16.row.col.f32.bf16.bf16.f32 " \
    "{%0,%1,%2,%3},{%4,%5,%6,%7},{%8,%9},{%10,%11,%12,%13};" \
    : "=f"(d[0]),"=f"(d[1]),"=f"(d[2]),"=f"(d[3]) \
    : "r"(a0),"r"(a1),"r"(a2),"r"(a3),"r"(b0),"r"(b1), \
      "f"(0.f),"f"(0.f),"f"(0.f),"f"(0.f))

#define MMA_BF16(d,a0,a1,a2,a3,b0,b1) \
  asm volatile("mma.sync.aligned.m16n8k16.row.col.f32.bf16.bf16.f32 " \
    "{%0,%1,%2,%3},{%4,%5,%6,%7},{%8,%9},{%0,%1,%2,%3};" \
    : "+f"(d[0]),"+f"(d[1]),"+f"(d[2]),"+f"(d[3]) \
    : "r"(a0),"r"(a1),"r"(a2),"r"(a3),"r"(b0),"r"(b1))

#define MMA_TF32(d,a,b) \
  asm volatile("mma.sync.aligned.m16n8k8.row.col.f32.tf32.tf32.f32 " \
    "{%0,%1,%2,%3},{%4,%5,%6,%7},{%8,%9},{%0,%1,%2,%3};" \
    : "+f"(d[0]),"+f"(d[1]),"+f"(d[2]),"+f"(d[3]) \
    : "r"((a)[0]),"r"((a)[1]),"r"((a)[2]),"r"((a)[3]),"r"((b)[0]),"r"((b)[1]))

#define CP_ASYNC16(saddr, gptr) \
  asm volatile("cp.async.ca.shared.global [%0],[%1],16;" :: "r"(saddr), "l"(gptr))
#define CP_COMMIT() asm volatile("cp.async.commit_group;")
#define CP_WAIT0()  asm volatile("cp.async.wait_group 0;")

#define EX2(d,s) asm("ex2.approx.f32 %0,%1;" : "=f"(d) : "f"(s))

__device__ __forceinline__ unsigned cvt_tf32(float f) {
    unsigned u; asm("cvt.rna.tf32.f32 %0,%1;" : "=r"(u) : "f"(f)); return u;
}
__device__ __forceinline__ unsigned pack_bf16(float a, float b) {
    __nv_bfloat162 t = __floats2bfloat162_rn(a, b);
    return *(unsigned*)&t;
}
__device__ __forceinline__ unsigned smem_u32(const void* p) {
    return (unsigned)__cvta_generic_to_shared(p);
}

__device__ __forceinline__ void ln_row(float4& v, const float4& gg, const float4& gb) {
    float s  = v.x + v.y + v.z + v.w;
    float sq = v.x*v.x + v.y*v.y + v.z*v.z + v.w*v.w;
    #pragma unroll
    for (int off = 16; off; off >>= 1) {
        s  += __shfl_xor_sync(0xffffffffu, s,  off);
        sq += __shfl_xor_sync(0xffffffffu, sq, off);
    }
    const float mean = s * (1.f/128.f);
    const float var  = sq * (1.f/128.f) - mean * mean;
    const float r    = rsqrtf(var + 1e-5f);
    v.x = (v.x - mean) * r * gg.x + gb.x;
    v.y = (v.y - mean) * r * gg.y + gb.y;
    v.z = (v.z - mean) * r * gg.z + gb.z;
    v.w = (v.w - mean) * r * gg.w + gb.w;
}

// async-stage [128][128] fp32 -> smem [128][132] raw bits (tf32 via HW trunc)
template<int NT>
__device__ __forceinline__ void stage_W_async(const float* __restrict__ W, float* Ws, int tid) {
    #pragma unroll
    for (int i = 0; i < 4096 / NT; i++) {
        const int f4 = tid + i * NT;
        const int row = f4 >> 5, c = (f4 & 31) * 4;
        CP_ASYNC16(smem_u32(&Ws[row * 132 + c]), W + (size_t)row * C_ + c);
    }
}

// 64x128x128 MMA, 16 warps, warp tile 16x32
__device__ __forceinline__ void mma_64x128(
    const unsigned* Au, const unsigned* Wu, int mw, int nw, int grp, int tig,
    float acc[4][4])
{
    const int r = mw * 16 + grp;
    #pragma unroll
    for (int ks = 0; ks < 16; ks++) {
        const int kb = ks * 8;
        unsigned af[4], bf[4][2];
        af[0] = Au[r * 132 + kb + tig];
        af[1] = Au[(r + 8) * 132 + kb + tig];
        af[2] = Au[r * 132 + kb + tig + 4];
        af[3] = Au[(r + 8) * 132 + kb + tig + 4];
        #pragma unroll
        for (int nt = 0; nt < 4; nt++) {
            const int rr = nw * 32 + nt * 8 + grp;
            bf[nt][0] = Wu[rr * 132 + kb + tig];
            bf[nt][1] = Wu[rr * 132 + kb + tig + 4];
        }
        #pragma unroll
        for (int nt = 0; nt < 4; nt++)
            MMA_TF32(acc[nt], af, bf[nt]);
    }
}

// 128x128x128 MMA (16 warps, warp tile 32x32): acc[2][4][4]
__device__ __forceinline__ void mma_w32x32(
    const unsigned* Au, const unsigned* Wu, int mw, int nw, int grp, int tig,
    float acc[2][4][4])
{
    #pragma unroll
    for (int ks = 0; ks < 16; ks++) {
        const int kb = ks * 8;
        unsigned af[2][4], bf[4][2];
        #pragma unroll
        for (int mt = 0; mt < 2; mt++) {
            const int r = mw * 32 + mt * 16 + grp;
            af[mt][0] = Au[r * 132 + kb + tig];
            af[mt][1] = Au[(r + 8) * 132 + kb + tig];
            af[mt][2] = Au[r * 132 + kb + tig + 4];
            af[mt][3] = Au[(r + 8) * 132 + kb + tig + 4];
        }
        #pragma unroll
        for (int nt = 0; nt < 4; nt++) {
            const int r = nw * 32 + nt * 8 + grp;
            bf[nt][0] = Wu[r * 132 + kb + tig];
            bf[nt][1] = Wu[r * 132 + kb + tig + 4];
        }
        #pragma unroll
        for (int mt = 0; mt < 2; mt++)
            #pragma unroll
            for (int nt = 0; nt < 4; nt++)
                MMA_TF32(acc[mt][nt], af[mt], bf[nt]);
    }
}

// ---------------- [B,C,L] -> [B,L,C] + pos encoding (+ mask detect in block 0) ----------------
__global__ void k_in2work(const float* __restrict__ x, float* __restrict__ out,
                          const unsigned char* __restrict__ m) {
    __shared__ float tile[32][33];
    __shared__ int sdet;
    const int b  = blockIdx.z;
    const int l0 = blockIdx.x * 32;
    const int c0 = blockIdx.y * 32;
    const int tx = threadIdx.x, ty = threadIdx.y;
    const int tid = ty * 32 + tx;
    const bool det = (blockIdx.x == 0 && blockIdx.y == 0 && blockIdx.z == 0);
    if (det) {
        if (tid == 0) sdet = 0;
        __syncthreads();
        int nz = 0;
        for (int i = tid; i < NTOK; i += 256)
            if ((i & 3) && m[i]) nz = 1;
        if (nz) atomicOr(&sdet, 1);
        __syncthreads();
        if (tid == 0) g_mask_int = (sdet == 0) ? 1 : 0;
    }
    #pragma unroll
    for (int j = 0; j < 4; j++)
        tile[ty + 8*j][tx] = x[((size_t)b*C_ + (c0 + ty + 8*j))*L_ + l0 + tx];
    __syncthreads();
    const int c = c0 + tx;
    const float fi = (float)c;
    float freq, phase;
    if (c & 1) { freq = -powf(10000.f, (1.f - fi) * (1.f/128.f)); phase = 1.57079632679489662f; }
    else       { freq =  powf(10000.f, -fi * (1.f/128.f));        phase = 0.f; }
    #pragma unroll
    for (int j = 0; j < 4; j++) {
        const int l = l0 + ty + 8*j;
        out[((size_t)b*L_ + l)*C_ + c] = tile[tx][ty + 8*j] + sinf((float)l * freq + phase);
    }
}

// ---------------- [B,L,C] -> [B,C,L] ----------------
__global__ void k_work2out(const float* __restrict__ in, float* __restrict__ out) {
    __shared__ float tile[32][33];
    const int b  = blockIdx.z;
    const int l0 = blockIdx.x * 32;
    const int c0 = blockIdx.y * 32;
    const int tx = threadIdx.x, ty = threadIdx.y;
    #pragma unroll
    for (int j = 0; j < 4; j++)
        tile[ty + 8*j][tx] = in[((size_t)b*L_ + (l0 + ty + 8*j))*C_ + c0 + tx];
    __syncthreads();
    #pragma unroll
    for (int j = 0; j < 4; j++)
        out[((size_t)b*C_ + (c0 + ty + 8*j))*L_ + l0 + tx] = tile[tx][ty + 8*j];
}

// =====================================================================
// Fused conv block (R13 winner, FROZEN)
// =====================================================================
__global__ void __launch_bounds__(512, 2) k_convblock(
    const float* __restrict__ in, const float* __restrict__ dw,
    const float* __restrict__ pw, const float* __restrict__ pb,
    const float* __restrict__ g,  const float* __restrict__ bb,
    float* __restrict__ out)
{
    extern __shared__ float sm[];
    float* y   = sm;                       // [70][132]; rows 0..63 become As
    float* Ws  = y  + 70 * 132;            // [128][132] raw fp32
    float* dwT = Ws + 128 * 132;           // [7][128]
    const int tid = threadIdx.x;
    const int b  = blockIdx.x >> 4;
    const int l0 = (blockIdx.x & 15) * 64;
    const int warp = tid >> 5, lane = tid & 31;

    stage_W_async<512>(pw, Ws, tid);
    CP_COMMIT();
    for (int i = tid; i < 896; i += 512) {
        const int k = i >> 7, c = i & 127;
        dwT[i] = dw[c * 7 + k];
    }
    {
        const float4 gg = *(const float4*)(g  + lane * 4);
        const float4 gb = *(const float4*)(bb + lane * 4);
        for (int r = warp; r < 70; r += 16) {
            const int l = l0 - 3 + r;
            float4 v = make_float4(0.f, 0.f, 0.f, 0.f);
            if (l >= 0 && l < L_) {
                v = *(const float4*)(in + ((size_t)(b * L_ + l)) * C_ + lane * 4);
                ln_row(v, gg, gb);
            } else {
                ln_row(v, gg, gb);   // keep warp converged
                v = make_float4(0.f, 0.f, 0.f, 0.f);
            }
            *(float4*)&y[r * 132 + lane * 4] = v;
        }
    }
    CP_WAIT0();
    __syncthreads();

    uint2 racc[8];
    {
        const int p  = tid & 63;
        const int lb = (tid >> 6) * 8;
        const int cb = p * 2;
        float2 wk[7];
        #pragma unroll
        for (int k = 0; k < 7; k++) wk[k] = *(const float2*)&dwT[k * 128 + cb];
        float2 w0 = *(const float2*)&y[(lb + 0) * 132 + cb];
        float2 w1 = *(const float2*)&y[(lb + 1) * 132 + cb];
        float2 w2 = *(const float2*)&y[(lb + 2) * 132 + cb];
        float2 w3 = *(const float2*)&y[(lb + 3) * 132 + cb];
        float2 w4 = *(const float2*)&y[(lb + 4) * 132 + cb];
        float2 w5 = *(const float2*)&y[(lb + 5) * 132 + cb];
        #pragma unroll
        for (int i = 0; i < 8; i++) {
            const float2 w6 = *(const float2*)&y[(lb + i + 6) * 132 + cb];
            float ax = wk[0].x * w0.x + wk[1].x * w1.x + wk[2].x * w2.x
                     + wk[3].x * w3.x + wk[4].x * w4.x + wk[5].x * w5.x
                     + wk[6].x * w6.x;
            float ay = wk[0].y * w0.y + wk[1].y * w1.y + wk[2].y * w2.y
                     + wk[3].y * w3.y + wk[4].y * w4.y + wk[5].y * w5.y
                     + wk[6].y * w6.y;
            racc[i].x = cvt_tf32(ax);
            racc[i].y = cvt_tf32(ay);
            w0 = w1; w1 = w2; w2 = w3; w3 = w4; w4 = w5; w5 = w6;
        }
    }
    __syncthreads();
    {
        const int p  = tid & 63;
        const int lb = (tid >> 6) * 8;
        const int cb = p * 2;
        #pragma unroll
        for (int i = 0; i < 8; i++)
            *(uint2*)&y[(lb + i) * 132 + cb] = racc[i];
    }
    __syncthreads();

    const int grp = lane >> 2, tig = lane & 3;
    const int mw = warp >> 2, nw = warp & 3;
    float acc[4][4];
    #pragma unroll
    for (int nt = 0; nt < 4; nt++)
        #pragma unroll
        for (int q = 0; q < 4; q++) acc[nt][q] = 0.f;

    mma_64x128((const unsigned*)y, (const unsigned*)Ws, mw, nw, grp, tig, acc);

    #pragma unroll
    for (int nt = 0; nt < 4; nt++) {
        const int col = nw * 32 + nt * 8 + tig * 2;
        const float2 bv = *(const float2*)(pb + col);
        const int rl = mw * 16 + grp;
        const size_t r0 = (size_t)(b * L_ + l0 + rl) * C_ + col;
        const size_t r1 = (size_t)(b * L_ + l0 + rl + 8) * C_ + col;
        float2 v0 = make_float2(fmaxf(acc[nt][0] + bv.x, 0.f), fmaxf(acc[nt][1] + bv.y, 0.f));
        float2 v1 = make_float2(fmaxf(acc[nt][2] + bv.x, 0.f), fmaxf(acc[nt][3] + bv.y, 0.f));
        const float2 q0 = *(const float2*)(in + r0);
        const float2 q1 = *(const float2*)(in + r1);
        v0.x += q0.x; v0.y += q0.y; v1.x += q1.x; v1.y += q1.y;
        *(float2*)(out + r0) = v0;
        *(float2*)(out + r1) = v1;
    }
}

// =====================================================================
// tf32 GEMM, 128-token tiles, cp.async staging
// =====================================================================
template<bool LNA, bool RELU, bool ADDRES>
__global__ void __launch_bounds__(512) k_gemm_tf32(
    const float* __restrict__ A, const float* __restrict__ W,
    const float* __restrict__ bias, const float* __restrict__ res,
    float* __restrict__ out,
    const float* __restrict__ g, const float* __restrict__ bb)
{
    extern __shared__ float sm[];
    float* As = sm;                        // [128][132]
    float* Ws = sm + 128 * 132;            // [128][132]
    const int tid = threadIdx.x;
    const int m0 = blockIdx.x * 128;
    const int warp = tid >> 5, lane = tid & 31;

    stage_W_async<512>(W, Ws, tid);
    if (LNA) {
        CP_COMMIT();
        const float4 gg = *(const float4*)(g  + lane * 4);
        const float4 gb = *(const float4*)(bb + lane * 4);
        for (int r = warp; r < 128; r += 16) {
            float4 v = *(const float4*)(A + (size_t)(m0 + r) * C_ + lane * 4);
            ln_row(v, gg, gb);
            uint4 u;
            u.x = cvt_tf32(v.x); u.y = cvt_tf32(v.y); u.z = cvt_tf32(v.z); u.w = cvt_tf32(v.w);
            *(uint4*)&As[r * 132 + lane * 4] = u;
        }
    } else {
        #pragma unroll
        for (int i = 0; i < 8; i++) {
            const int f4 = tid + i * 512;
            const int row = f4 >> 5, c = (f4 & 31) * 4;
            CP_ASYNC16(smem_u32(&As[row * 132 + c]), A + (size_t)(m0 + row) * C_ + c);
        }
        CP_COMMIT();
    }
    CP_WAIT0();
    __syncthreads();

    const int grp = lane >> 2, tig = lane & 3;
    const int mw = warp >> 2, nw = warp & 3;
    float acc[2][4][4];
    #pragma unroll
    for (int mt = 0; mt < 2; mt++)
        #pragma unroll
        for (int nt = 0; nt < 4; nt++)
            #pragma unroll
            for (int q = 0; q < 4; q++) acc[mt][nt][q] = 0.f;

    mma_w32x32((const unsigned*)As, (const unsigned*)Ws, mw, nw, grp, tig, acc);

    #pragma unroll
    for (int nt = 0; nt < 4; nt++) {
        const int col = nw * 32 + nt * 8 + tig * 2;
        const float2 bv = *(const float2*)(bias + col);
        #pragma unroll
        for (int mt = 0; mt < 2; mt++) {
            const int row = m0 + mw * 32 + mt * 16 + grp;
            float2 v0 = make_float2(acc[mt][nt][0] + bv.x, acc[mt][nt][1] + bv.y);
            float2 v1 = make_float2(acc[mt][nt][2] + bv.x, acc[mt][nt][3] + bv.y);
            if (RELU) {
                v0.x = fmaxf(v0.x, 0.f); v0.y = fmaxf(v0.y, 0.f);
                v1.x = fmaxf(v1.x, 0.f); v1.y = fmaxf(v1.y, 0.f);
            }
            if (ADDRES) {
                const float2 r0 = *(const float2*)(res + (size_t)row * C_ + col);
                const float2 r1 = *(const float2*)(res + (size_t)(row + 8) * C_ + col);
                v0.x += r0.x; v0.y += r0.y; v1.x += r1.x; v1.y += r1.y;
            }
            *(float2*)(out + (size_t)row * C_ + col) = v0;
            *(float2*)(out + (size_t)(row + 8) * C_ + col) = v1;
        }
    }
}

// =====================================================================
// Fused QKV: 128-token tiles, LN once, cp.async W pipelined across j
// =====================================================================
__global__ void __launch_bounds__(512) k_qkv3(
    const float* __restrict__ A,
    const float* __restrict__ wq, const float* __restrict__ bq, float* __restrict__ oq,
    const float* __restrict__ wk, const float* __restrict__ bk, float* __restrict__ ok,
    const float* __restrict__ wv, const float* __restrict__ bv, float* __restrict__ ov,
    const float* __restrict__ g, const float* __restrict__ bb)
{
    extern __shared__ float sm[];
    float* As = sm;
    float* Ws = sm + 128 * 132;
    const int tid = threadIdx.x;
    const int m0 = blockIdx.x * 128;
    const int warp = tid >> 5, lane = tid & 31;

    const float* Wj[3]   = {wq, wk, wv};
    const float* bj[3]   = {bq, bk, bv};
    float*       outj[3] = {oq, ok, ov};

    stage_W_async<512>(Wj[0], Ws, tid);
    CP_COMMIT();
    {
        const float4 gg = *(const float4*)(g  + lane * 4);
        const float4 gb = *(const float4*)(bb + lane * 4);
        for (int r = warp; r < 128; r += 16) {
            float4 v = *(const float4*)(A + (size_t)(m0 + r) * C_ + lane * 4);
            ln_row(v, gg, gb);
            uint4 u;
            u.x = cvt_tf32(v.x); u.y = cvt_tf32(v.y); u.z = cvt_tf32(v.z); u.w = cvt_tf32(v.w);
            *(uint4*)&As[r * 132 + lane * 4] = u;
        }
    }

    const int grp = lane >> 2, tig = lane & 3;
    const int mw = warp >> 2, nw = warp & 3;

    #pragma unroll 1
    for (int j = 0; j < 3; j++) {
        CP_WAIT0();
        __syncthreads();              // Ws[j] + As ready

        float acc[2][4][4];
        #pragma unroll
        for (int mt = 0; mt < 2; mt++)
            #pragma unroll
            for (int nt = 0; nt < 4; nt++)
                #pragma unroll
                for (int q = 0; q < 4; q++) acc[mt][nt][q] = 0.f;

        mma_w32x32((const unsigned*)As, (const unsigned*)Ws, mw, nw, grp, tig, acc);
        __syncthreads();              // all Ws reads done before overwrite

        if (j < 2) { stage_W_async<512>(Wj[j + 1], Ws, tid); CP_COMMIT(); }

        #pragma unroll
        for (int nt = 0; nt < 4; nt++) {
            const int col = nw * 32 + nt * 8 + tig * 2;
            const float2 bvv = *(const float2*)(bj[j] + col);
            #pragma unroll
            for (int mt = 0; mt < 2; mt++) {
                const int row = m0 + mw * 32 + mt * 16 + grp;
                float2 v0 = make_float2(acc[mt][nt][0] + bvv.x, acc[mt][nt][1] + bvv.y);
                float2 v1 = make_float2(acc[mt][nt][2] + bvv.x, acc[mt][nt][3] + bvv.y);
                *(float2*)(outj[j] + (size_t)row * C_ + col) = v0;
                *(float2*)(outj[j] + (size_t)(row + 8) * C_ + col) = v1;
            }
        }
    }
}

// ---------------- flash attention: base-2 scores, ex2-only softmax,
//                  mask via zeroed V rows + mask-fragment row sums ----------------
__global__ void __launch_bounds__(256) k_attn(
    const float* __restrict__ Q, const float* __restrict__ K,
    const float* __restrict__ V, const void* __restrict__ maskp,
    float* __restrict__ O)
{
    __shared__ __nv_bfloat16 Qs[128 * 24];
    __shared__ __nv_bfloat16 Ks[2][64 * 24];
    __shared__ __nv_bfloat16 Vs[2][64 * 24];
    __shared__ __nv_bfloat16 mb[1024];     // 1.0 = keep, 0.0 = masked
    const int tid = threadIdx.x;
    const int w = tid >> 5, l = tid & 31;
    const int grp = l >> 2, tig = l & 3;
    const int b = blockIdx.y >> 3, h = blockIdx.y & 7;
    const int q0 = blockIdx.x * 128;
    const int mint = g_mask_int;
    const int* mi = (const int*)maskp;
    const unsigned char* mu = (const unsigned char*)maskp;
    // 0.25 / sqrt: already 1/sqrt(DK); fold log2(e) so exp == ex2
    const float QSCALE = 0.25f * 1.44269504088896340736f;

    #pragma unroll
    for (int i = tid; i < 1024; i += 256) {
        const int mv = mint ? mi[b * L_ + i] : (int)mu[b * L_ + i];
        mb[i] = __float2bfloat16(mv ? 0.f : 1.f);
    }
    #pragma unroll
    for (int i = tid; i < 512; i += 256) {
        const int row = i >> 2, c4 = (i & 3) * 4;
        float4 f = *(const float4*)(Q + ((size_t)(b * L_ + q0 + row) * C_) + h * 16 + c4);
        __nv_bfloat162* dst = (__nv_bfloat162*)(Qs + row * 24 + c4);
        dst[0] = __floats2bfloat162_rn(f.x * QSCALE, f.y * QSCALE);
        dst[1] = __floats2bfloat162_rn(f.z * QSCALE, f.w * QSCALE);
    }
    __syncthreads();   // mb ready before first V zeroing

    const int krow = tid >> 2, kc4 = (tid & 3) * 4;
    {
        const float m0v = __bfloat162float(mb[krow]);
        float4 fk = *(const float4*)(K + ((size_t)(b * L_ + krow) * C_) + h * 16 + kc4);
        float4 fv = *(const float4*)(V + ((size_t)(b * L_ + krow) * C_) + h * 16 + kc4);
        __nv_bfloat162* dk = (__nv_bfloat162*)(Ks[0] + krow * 24 + kc4);
        dk[0] = __floats2bfloat162_rn(fk.x, fk.y);
        dk[1] = __floats2bfloat162_rn(fk.z, fk.w);
        __nv_bfloat162* dv = (__nv_bfloat162*)(Vs[0] + krow * 24 + kc4);
        dv[0] = __floats2bfloat162_rn(fv.x * m0v, fv.y * m0v);
        dv[1] = __floats2bfloat162_rn(fv.z * m0v, fv.w * m0v);
    }
    __syncthreads();

    unsigned qa0, qa1, qa2, qa3;
    {
        const __nv_bfloat16* p = Qs + (w * 16 + (l & 15)) * 24 + ((l >> 4) * 8);
        unsigned ad = smem_u32(p);
        LDMX4(qa0, qa1, qa2, qa3, ad);
    }

    float o0[4] = {0,0,0,0}, o1[4] = {0,0,0,0};
    float sacc[4] = {0,0,0,0};

    for (int kt = 0; kt < 16; kt++) {
        const int buf = kt & 1;
        float4 fk, fv;
        if (kt < 15) {
            const size_t base = ((size_t)(b * L_ + (kt + 1) * 64 + krow) * C_) + h * 16 + kc4;
            fk = *(const float4*)(K + base);
            fv = *(const float4*)(V + base);
        }
        const int k0 = kt * 64;

        float s[8][4];
        #pragma unroll
        for (int ntp = 0; ntp < 4; ntp++) {
            const int nb = ntp * 16;
            const __nv_bfloat16* p = Ks[buf] + (nb + ((l >> 4) & 1) * 8 + (l & 7)) * 24 + ((l >> 3) & 1) * 8;
            unsigned ad = smem_u32(p);
            unsigned kb0, kb1, kb2, kb3;
            LDMX4(kb0, kb1, kb2, kb3, ad);
            MMA_BF16_Z(s[2*ntp],     qa0, qa1, qa2, qa3, kb0, kb1);
            MMA_BF16_Z(s[2*ntp + 1], qa0, qa1, qa2, qa3, kb2, kb3);
        }

        // ex2-only softmax numerators (no mask, no scaling, no sum here)
        unsigned pa[4][4];
        #pragma unroll
        for (int nt = 0; nt < 8; nt++) {
            float p0, p1, p2, p3;
            EX2(p0, s[nt][0]); EX2(p1, s[nt][1]);
            EX2(p2, s[nt][2]); EX2(p3, s[nt][3]);
            pa[nt >> 1][(nt & 1) * 2 + 0] = pack_bf16(p0, p1);
            pa[nt >> 1][(nt & 1) * 2 + 1] = pack_bf16(p2, p3);
        }

        #pragma unroll
        for (int kk = 0; kk < 4; kk++) {
            const __nv_bfloat16* p = Vs[buf] + (kk * 16 + ((l >> 3) & 1) * 8 + (l & 7)) * 24 + ((l >> 4) & 1) * 8;
            unsigned ad = smem_u32(p);
            unsigned vb0, vb1, vb2, vb3;
            LDMX4T(vb0, vb1, vb2, vb3, ad);
            MMA_BF16(o0, pa[kk][0], pa[kk][1], pa[kk][2], pa[kk][3], vb0, vb1);
            MMA_BF16(o1, pa[kk][0], pa[kk][1], pa[kk][2], pa[kk][3], vb2, vb3);
            // row sums with mask fragment: B[k][n] = mb[key] (excludes masked keys)
            const unsigned mb0 = *(const unsigned*)&mb[k0 + kk * 16 + tig * 2];
            const unsigned mb1 = *(const unsigned*)&mb[k0 + kk * 16 + tig * 2 + 8];
            MMA_BF16(sacc, pa[kk][0], pa[kk][1], pa[kk][2], pa[kk][3], mb0, mb1);
        }

        if (kt < 15) {
            const float mv2 = __bfloat162float(mb[(kt + 1) * 64 + krow]);
            __nv_bfloat162* dk = (__nv_bfloat162*)(Ks[buf ^ 1] + krow * 24 + kc4);
            dk[0] = __floats2bfloat162_rn(fk.x, fk.y);
            dk[1] = __floats2bfloat162_rn(fk.z, fk.w);
            __nv_bfloat162* dv = (__nv_bfloat162*)(Vs[buf ^ 1] + krow * 24 + kc4);
            dv[0] = __floats2bfloat162_rn(fv.x * mv2, fv.y * mv2);
            dv[1] = __floats2bfloat162_rn(fv.z * mv2, fv.w * mv2);
            __syncthreads();
        }
    }

    const float i0 = 1.f / sacc[0], i1 = 1.f / sacc[2];
    const int row0 = q0 + w * 16 + grp, row1 = row0 + 8;
    const int colb = h * 16 + tig * 2;
    *(float2*)(O + (size_t)(b * L_ + row0) * C_ + colb)     = make_float2(o0[0]*i0, o0[1]*i0);
    *(float2*)(O + (size_t)(b * L_ + row1) * C_ + colb)     = make_float2(o0[2]*i1, o0[3]*i1);
    *(float2*)(O + (size_t)(b * L_ + row0) * C_ + colb + 8) = make_float2(o1[0]*i0, o1[1]*i0);
    *(float2*)(O + (size_t)(b * L_ + row1) * C_ + colb + 8) = make_float2(o1[2]*i1, o1[3]*i1);
}

// ---------------- launcher ----------------
extern "C" void kernel_launch(void* const* d_in, const int* in_sizes, int n_in,
                              void* d_out, int out_size)
{
    const float* x    = (const float*)d_in[0];
    const void*  mask = d_in[1];
    const float* dw_w = (const float*)d_in[2];
    const float* pw_w = (const float*)d_in[3];
    const float* pw_b = (const float*)d_in[4];
    const float* ng   = (const float*)d_in[5];
    const float* nb   = (const float*)d_in[6];
    const float* wq = (const float*)d_in[7];   const float* bq = (const float*)d_in[8];
    const float* wk = (const float*)d_in[9];   const float* bk = (const float*)d_in[10];
    const float* wv = (const float*)d_in[11];  const float* bv = (const float*)d_in[12];
    const float* wo = (const float*)d_in[13];  const float* bo = (const float*)d_in[14];
    const float* w1 = (const float*)d_in[15];  const float* b1 = (const float*)d_in[16];
    const float* w2 = (const float*)d_in[17];  const float* b2 = (const float*)d_in[18];
    float* out = (float*)d_out;

    float *cur, *ln, *t1, *q, *k, *v;
    { void* p; cudaGetSymbolAddress(&p, g_cur); cur = (float*)p; }
    { void* p; cudaGetSymbolAddress(&p, g_ln);  ln  = (float*)p; }
    { void* p; cudaGetSymbolAddress(&p, g_t1);  t1  = (float*)p; }
    { void* p; cudaGetSymbolAddress(&p, g_q);   q   = (float*)p; }
    { void* p; cudaGetSymbolAddress(&p, g_k);   k   = (float*)p; }
    { void* p; cudaGetSymbolAddress(&p, g_v);   v   = (float*)p; }

    const int SMC = (70 * 132 + 128 * 132 + 896) * 4;   // 108128 B
    const int SMG = 2 * 128 * 132 * 4;                  // 135168 B
    cudaFuncSetAttribute(k_convblock, cudaFuncAttributeMaxDynamicSharedMemorySize, SMC);
    cudaFuncSetAttribute(k_qkv3, cudaFuncAttributeMaxDynamicSharedMemorySize, SMG);
    cudaFuncSetAttribute(k_gemm_tf32<false,false,true >, cudaFuncAttributeMaxDynamicSharedMemorySize, SMG);
    cudaFuncSetAttribute(k_gemm_tf32<true ,true ,false>, cudaFuncAttributeMaxDynamicSharedMemorySize, SMG);

    const dim3 tgrid(32, 4, 16), tblk(32, 8);

    k_in2work<<<tgrid, tblk>>>(x, cur, (const unsigned char*)mask);

    const float* cin[4]  = {cur, t1, cur, t1};
    float*       cout[4] = {t1, cur, t1, cur};
    for (int i = 0; i < NCONV_; i++) {
        k_convblock<<<256, 512, SMC>>>(cin[i], dw_w + i * C_ * 7, pw_w + i * C_ * C_,
                                       pw_b + i * C_, ng + i * C_, nb + i * C_, cout[i]);
    }

    k_qkv3<<<128, 512, SMG>>>(cur, wq, bq, q, wk, bk, k, wv, bv, v,
                              ng + NCONV_ * C_, nb + NCONV_ * C_);
    k_attn<<<dim3(8, 128), 256>>>(q, k, v, mask, ln);
    k_gemm_tf32<false,false,true ><<<128, 512, SMG>>>(ln, wo, bo, cur, cur, nullptr, nullptr);

    k_gemm_tf32<true ,true ,false><<<128, 512, SMG>>>(cur, w1, b1, nullptr, t1,
                                                      ng + (NCONV_ + 1) * C_, nb + (NCONV_ + 1) * C_);
    k_gemm_tf32<false,false,true ><<<128, 512, SMG>>>(t1, w2, b2, cur, cur, nullptr, nullptr);

    k_work2out<<<tgrid, tblk>>>(cur, out);
}